// round 1
// baseline (speedup 1.0000x reference)
#include <cuda_runtime.h>

#define NN 256
#define BB 2
#define NNODE (BB*NN)

// scratch: G[node][f*4+c], f in [0,33) where f==32 is the bias (constant-1) feature
__device__ float g_G[NNODE][33*4];

// ---------------------------------------------------------------------------
// Kernel B: per-(b,n) edge reduction.
// h[m,f] = relu(edge_attr[m,:] @ fc_w1[:,f] + fc_b1[f])
// G[f,c] = sum_m h'[m,f] * edge_sh[m,c] * mask[m] * (m != n)
// ---------------------------------------------------------------------------
__global__ __launch_bounds__(256) void edge_kernel(
    const float* __restrict__ edge_attr,
    const float* __restrict__ edge_sh,
    const float* __restrict__ mask,
    const float* __restrict__ fc_w1,
    const float* __restrict__ fc_b1)
{
    __shared__ __align__(16) float ea[NN * 32];   // [m][j]  32 KB
    __shared__ __align__(16) float sh[NN * 4];    // [m][c]   4 KB
    __shared__ float w1[32 * 32];                 // [j][f]   4 KB
    __shared__ float b1s[32];
    __shared__ float msk[NN];
    __shared__ float Gp[8][132];                  // per-mg partial G

    const int node = blockIdx.x;         // b*256 + n
    const int b = node >> 8;
    const int n = node & 255;
    const int t = threadIdx.x;

    const float4* ea_g = (const float4*)(edge_attr + (size_t)node * NN * 32);
    const float4* sh_g = (const float4*)(edge_sh + (size_t)node * NN * 4);
    float4* ea4 = (float4*)ea;
    float4* sh4 = (float4*)sh;

    #pragma unroll
    for (int i = t; i < NN * 8; i += 256) ea4[i] = ea_g[i];
    if (t < NN) sh4[t] = sh_g[t];
    for (int i = t; i < 32 * 32; i += 256) w1[i] = fc_w1[i];
    if (t < 32) b1s[t] = fc_b1[t];
    msk[t] = mask[b * NN + t];
    __syncthreads();

    const int f  = t & 31;   // lane = feature column
    const int mg = t >> 5;   // warp = m-group

    // hoist this thread's W1 column into registers
    float w1c[32];
    #pragma unroll
    for (int j = 0; j < 32; j++) w1c[j] = w1[j * 32 + f];
    const float bias1 = b1s[f];

    float acc0 = 0.f, acc1 = 0.f, acc2 = 0.f, acc3 = 0.f;       // h-weighted
    float bc0 = 0.f, bc1 = 0.f, bc2 = 0.f, bc3 = 0.f;           // bias feature

    for (int m = mg; m < NN; m += 8) {
        const float4* row = (const float4*)(ea + m * 32);
        float dA = bias1, dB = 0.f;
        #pragma unroll
        for (int q = 0; q < 8; q += 2) {
            float4 v0 = row[q];
            float4 v1 = row[q + 1];
            dA += v0.x * w1c[4*q+0] + v0.y * w1c[4*q+1]
                + v0.z * w1c[4*q+2] + v0.w * w1c[4*q+3];
            dB += v1.x * w1c[4*q+4] + v1.y * w1c[4*q+5]
                + v1.z * w1c[4*q+6] + v1.w * w1c[4*q+7];
        }
        float h = fmaxf(dA + dB, 0.0f);
        float mf = msk[m] * (m != n ? 1.0f : 0.0f);
        float hm = h * mf;
        float s0 = sh[m*4+0], s1 = sh[m*4+1], s2 = sh[m*4+2], s3 = sh[m*4+3];
        acc0 += hm * s0; acc1 += hm * s1; acc2 += hm * s2; acc3 += hm * s3;
        if (f == 0) { bc0 += mf * s0; bc1 += mf * s1; bc2 += mf * s2; bc3 += mf * s3; }
    }

    Gp[mg][f*4+0] = acc0;
    Gp[mg][f*4+1] = acc1;
    Gp[mg][f*4+2] = acc2;
    Gp[mg][f*4+3] = acc3;
    if (f == 0) {
        Gp[mg][32*4+0] = bc0;
        Gp[mg][32*4+1] = bc1;
        Gp[mg][32*4+2] = bc2;
        Gp[mg][32*4+3] = bc3;
    }
    __syncthreads();

    if (t < 132) {
        float s = 0.f;
        #pragma unroll
        for (int g = 0; g < 8; g++) s += Gp[g][t];
        g_G[node][t] = s;
    }
}

// ---------------------------------------------------------------------------
// Kernel C: per-node epilogue (2 nodes per block).
// R[c,k] = sum_f G[f,c] * W2'[f,k]  (W2' = [fc_w2; fc_b2], 33 x 1024)
// out_s[o]   = inv/dsum * ( sum_i s_in[i]*R[0][i*16+o]
//                          + (1/sqrt3) sum_{i,x} v_in[i,x]*R[1+x][256+i*16+o] )
// out_v[o,x] = inv/dsum * ( sum_i s_in[i]*R[1+x][512+i*16+o]
//                          + sum_i v_in[i,x]*R[0][768+i*16+o] )
// then output linear (/4) + residual.
// ---------------------------------------------------------------------------
__global__ __launch_bounds__(256) void node_kernel(
    const float* __restrict__ node_attr,
    const float* __restrict__ mask,
    const float* __restrict__ w_lin_in_s,
    const float* __restrict__ w_lin_in_v,
    const float* __restrict__ fc_w2,
    const float* __restrict__ fc_b2,
    const float* __restrict__ w_lin_out_s,
    const float* __restrict__ w_lin_out_v,
    float* __restrict__ out)
{
    __shared__ __align__(16) float Rsh[2][4][1024];   // 32 KB
    __shared__ float Gs[2][132];
    __shared__ float sinS[2][16];
    __shared__ float vinS[2][48];   // [o*3+x]
    __shared__ float wls[256], wlv[256], wos[256], wov[256];
    __shared__ float outsS[2][16], outvS[2][48];
    __shared__ float red[8];
    __shared__ float dsum_s;

    const int t = threadIdx.x;
    const int node0 = blockIdx.x * 2;
    const int b = node0 >> 8;

    wls[t & 255] = w_lin_in_s[t];     // t in [0,256)
    wlv[t] = w_lin_in_v[t];
    wos[t] = w_lin_out_s[t];
    wov[t] = w_lin_out_v[t];
    if (t < 132) {
        Gs[0][t] = g_G[node0][t];
        Gs[1][t] = g_G[node0 + 1][t];
    }
    // dsum = sum(mask[b,:]) - 1
    {
        float mv = mask[b * NN + t];
        #pragma unroll
        for (int o = 16; o; o >>= 1) mv += __shfl_xor_sync(0xFFFFFFFFu, mv, o);
        if ((t & 31) == 0) red[t >> 5] = mv;
    }
    __syncthreads();
    if (t == 0) {
        float s = 0.f;
        #pragma unroll
        for (int i = 0; i < 8; i++) s += red[i];
        dsum_s = s - 1.0f;
    }

    // s_in / v_in (irrep_linear on node_attr, /4)
    if (t < 128) {
        int nl = t >> 6, u = t & 63;
        const float* na = node_attr + (size_t)(node0 + nl) * 64;
        if (u < 16) {
            float s = 0.f;
            #pragma unroll
            for (int i = 0; i < 16; i++) s += na[i] * wls[i * 16 + u];
            sinS[nl][u] = s * 0.25f;
        } else {
            int idx = u - 16;
            int o = idx / 3, x = idx % 3;
            float s = 0.f;
            #pragma unroll
            for (int i = 0; i < 16; i++) s += na[16 + i * 3 + x] * wlv[i * 16 + o];
            vinS[nl][o * 3 + x] = s * 0.25f;
        }
    }
    __syncthreads();

    // R = G @ W2'   (thread t handles k = 4t..4t+3)
    float acc[2][4][4];
    #pragma unroll
    for (int nl = 0; nl < 2; nl++)
        #pragma unroll
        for (int c = 0; c < 4; c++)
            #pragma unroll
            for (int q = 0; q < 4; q++) acc[nl][c][q] = 0.f;

    const float4* W2 = (const float4*)fc_w2;   // [f][256] of float4
    for (int ff = 0; ff < 32; ff++) {
        float4 w = W2[ff * 256 + t];
        #pragma unroll
        for (int nl = 0; nl < 2; nl++) {
            #pragma unroll
            for (int c = 0; c < 4; c++) {
                float g = Gs[nl][ff * 4 + c];
                acc[nl][c][0] += g * w.x;
                acc[nl][c][1] += g * w.y;
                acc[nl][c][2] += g * w.z;
                acc[nl][c][3] += g * w.w;
            }
        }
    }
    {   // bias row (f = 32)
        float4 w = ((const float4*)fc_b2)[t];
        #pragma unroll
        for (int nl = 0; nl < 2; nl++) {
            #pragma unroll
            for (int c = 0; c < 4; c++) {
                float g = Gs[nl][32 * 4 + c];
                acc[nl][c][0] += g * w.x;
                acc[nl][c][1] += g * w.y;
                acc[nl][c][2] += g * w.z;
                acc[nl][c][3] += g * w.w;
            }
        }
    }
    #pragma unroll
    for (int nl = 0; nl < 2; nl++)
        #pragma unroll
        for (int c = 0; c < 4; c++)
            ((float4*)Rsh[nl][c])[t] =
                make_float4(acc[nl][c][0], acc[nl][c][1], acc[nl][c][2], acc[nl][c][3]);
    __syncthreads();

    const float INV_FAN = 0.1767766952966369f;   // 1/sqrt(32)
    const float RSQRT3  = 0.5773502691896258f;   // 1/sqrt(3)
    const float scale = INV_FAN / dsum_s;

    // irrep tensor-product outputs
    if (t < 128) {
        int nl = t >> 6, u = t & 63;
        if (u < 16) {
            int o = u;
            float s = 0.f;
            #pragma unroll
            for (int i = 0; i < 16; i++) s += sinS[nl][i] * Rsh[nl][0][i * 16 + o];
            float sv = 0.f;
            #pragma unroll
            for (int i = 0; i < 16; i++)
                #pragma unroll
                for (int x = 0; x < 3; x++)
                    sv += vinS[nl][i * 3 + x] * Rsh[nl][1 + x][256 + i * 16 + o];
            outsS[nl][o] = (s + sv * RSQRT3) * scale;
        } else {
            int idx = u - 16;
            int o = idx / 3, x = idx % 3;
            float s = 0.f;
            #pragma unroll
            for (int i = 0; i < 16; i++) s += sinS[nl][i] * Rsh[nl][1 + x][512 + i * 16 + o];
            #pragma unroll
            for (int i = 0; i < 16; i++) s += vinS[nl][i * 3 + x] * Rsh[nl][0][768 + i * 16 + o];
            outvS[nl][o * 3 + x] = s * scale;
        }
    }
    __syncthreads();

    // output linear (/4) + residual, write 64 floats per node
    if (t < 128) {
        int nl = t >> 6, u = t & 63;
        const float* na = node_attr + (size_t)(node0 + nl) * 64;
        float r;
        if (u < 16) {
            float s = 0.f;
            #pragma unroll
            for (int o = 0; o < 16; o++) s += outsS[nl][o] * wos[o * 16 + u];
            r = s * 0.25f + na[u];
        } else {
            int idx = u - 16;
            int o2 = idx / 3, x = idx % 3;
            float s = 0.f;
            #pragma unroll
            for (int o = 0; o < 16; o++) s += outvS[nl][o * 3 + x] * wov[o * 16 + o2];
            r = s * 0.25f + na[u];
        }
        out[(size_t)(node0 + nl) * 64 + u] = r;
    }
}

extern "C" void kernel_launch(void* const* d_in, const int* in_sizes, int n_in,
                              void* d_out, int out_size) {
    const float* node_attr    = (const float*)d_in[0];
    const float* edge_attr    = (const float*)d_in[1];
    const float* edge_sh      = (const float*)d_in[2];
    const float* mask         = (const float*)d_in[3];
    const float* w_lin_in_s   = (const float*)d_in[4];
    const float* w_lin_in_v   = (const float*)d_in[5];
    const float* fc_w1        = (const float*)d_in[6];
    const float* fc_b1        = (const float*)d_in[7];
    const float* fc_w2        = (const float*)d_in[8];
    const float* fc_b2        = (const float*)d_in[9];
    const float* w_lin_out_s  = (const float*)d_in[10];
    const float* w_lin_out_v  = (const float*)d_in[11];
    float* out = (float*)d_out;

    edge_kernel<<<NNODE, 256>>>(edge_attr, edge_sh, mask, fc_w1, fc_b1);
    node_kernel<<<NNODE / 2, 256>>>(node_attr, mask, w_lin_in_s, w_lin_in_v,
                                    fc_w2, fc_b2, w_lin_out_s, w_lin_out_v, out);
}

// round 2
// speedup vs baseline: 1.0707x; 1.0707x over previous
#include <cuda_runtime.h>

#define NN 256
#define BB 2
#define NNODE (BB*NN)

#define RSQRT3 0.5773502691896258f
#define INV_FAN 0.1767766952966369f   // 1/sqrt(32)

// scratch: G[node][f*4+c], f in [0,33) where f==32 is the bias (constant-1) feature
__device__ float g_G[NNODE][33*4];

#define PACK_F32X2(out, lo, hi) \
    asm("mov.b64 %0, {%1, %2};" : "=l"(out) : "f"(lo), "f"(hi))
#define UNPACK_F32X2(lo, hi, in) \
    asm("mov.b64 {%0, %1}, %2;" : "=f"(lo), "=f"(hi) : "l"(in))
#define FMA_F32X2(d, a, b, c) \
    asm("fma.rn.f32x2 %0, %1, %2, %3;" : "=l"(d) : "l"(a), "l"(b), "l"(c))

// ---------------------------------------------------------------------------
// Kernel A: per-(b,n) edge reduction (f32x2 packed).
// h[m,f] = relu(edge_attr[m,:] @ fc_w1[:,f] + fc_b1[f])
// G[f,c] = sum_m h[m,f] * edge_sh[m,c] * mask[m] * (m != n)   (f=32: h==1)
// ---------------------------------------------------------------------------
__global__ __launch_bounds__(256) void edge_kernel(
    const float* __restrict__ edge_attr,
    const float* __restrict__ edge_sh,
    const float* __restrict__ mask,
    const float* __restrict__ fc_w1,
    const float* __restrict__ fc_b1)
{
    __shared__ __align__(16) float ea[NN * 32];   // [m][j]  32 KB
    __shared__ __align__(16) float sh[NN * 4];    // [m][c]   4 KB
    __shared__ float w1s[32 * 32];                // [j][f]   4 KB
    __shared__ float b1s[32];
    __shared__ float msk[NN];                     // premultiplied with (m!=n)
    __shared__ float Gp[8][132];

    const int node = blockIdx.x;
    const int b = node >> 8;
    const int n = node & 255;
    const int t = threadIdx.x;

    const float4* ea_g = (const float4*)(edge_attr + (size_t)node * NN * 32);
    const float4* sh_g = (const float4*)(edge_sh + (size_t)node * NN * 4);
    float4* ea4 = (float4*)ea;
    float4* sh4 = (float4*)sh;

    #pragma unroll
    for (int i = t; i < NN * 8; i += 256) ea4[i] = ea_g[i];
    if (t < NN) sh4[t] = sh_g[t];
    for (int i = t; i < 32 * 32; i += 256) w1s[i] = fc_w1[i];
    if (t < 32) b1s[t] = fc_b1[t];
    msk[t] = mask[b * NN + t] * (t != n ? 1.0f : 0.0f);
    __syncthreads();

    const int f  = t & 31;   // lane = feature column
    const int mg = t >> 5;   // warp = m-group

    // pack this thread's W1 column into f32x2 registers
    unsigned long long w1p[16];
    #pragma unroll
    for (int j = 0; j < 16; j++)
        PACK_F32X2(w1p[j], w1s[(2*j) * 32 + f], w1s[(2*j+1) * 32 + f]);
    unsigned long long bias2;
    PACK_F32X2(bias2, b1s[f], 0.0f);

    unsigned long long acc01 = 0ULL, acc23 = 0ULL;   // h-weighted G accum
    unsigned long long bc01 = 0ULL, bc23 = 0ULL;     // bias feature (lane 0)

    for (int m = mg; m < NN; m += 8) {
        const ulonglong2* row = (const ulonglong2*)(ea + m * 32);
        unsigned long long dA = bias2, dB = 0ULL;
        #pragma unroll
        for (int q = 0; q < 4; q++) {
            ulonglong2 u0 = row[2*q];
            ulonglong2 u1 = row[2*q + 1];
            FMA_F32X2(dA, u0.x, w1p[4*q+0], dA);
            FMA_F32X2(dB, u0.y, w1p[4*q+1], dB);
            FMA_F32X2(dA, u1.x, w1p[4*q+2], dA);
            FMA_F32X2(dB, u1.y, w1p[4*q+3], dB);
        }
        float a0, a1, b0, b1;
        UNPACK_F32X2(a0, a1, dA);
        UNPACK_F32X2(b0, b1, dB);
        float h = fmaxf((a0 + a1) + (b0 + b1), 0.0f);
        float mf = msk[m];
        float hm = h * mf;
        unsigned long long hm2;
        PACK_F32X2(hm2, hm, hm);
        ulonglong2 s2 = ((const ulonglong2*)sh)[m];
        FMA_F32X2(acc01, hm2, s2.x, acc01);
        FMA_F32X2(acc23, hm2, s2.y, acc23);
        if (f == 0) {
            unsigned long long mf2;
            PACK_F32X2(mf2, mf, mf);
            FMA_F32X2(bc01, mf2, s2.x, bc01);
            FMA_F32X2(bc23, mf2, s2.y, bc23);
        }
    }

    float o0, o1, o2, o3;
    UNPACK_F32X2(o0, o1, acc01);
    UNPACK_F32X2(o2, o3, acc23);
    Gp[mg][f*4+0] = o0;
    Gp[mg][f*4+1] = o1;
    Gp[mg][f*4+2] = o2;
    Gp[mg][f*4+3] = o3;
    if (f == 0) {
        UNPACK_F32X2(o0, o1, bc01);
        UNPACK_F32X2(o2, o3, bc23);
        Gp[mg][128+0] = o0;
        Gp[mg][128+1] = o1;
        Gp[mg][128+2] = o2;
        Gp[mg][128+3] = o3;
    }
    __syncthreads();

    if (t < 132) {
        float s = 0.f;
        #pragma unroll
        for (int g = 0; g < 8; g++) s += Gp[g][t];
        g_G[node][t] = s;
    }
}

// ---------------------------------------------------------------------------
// Kernel B: per-node epilogue, 4 nodes/block, 128 blocks.
// One pass over W2' = [fc_w2; fc_b2] (33 x 1024), each element contributing
// directly to out_s / out_v with per-node coefficients; no R materialization.
// Then scale by INV_FAN/dsum, output linear (/4), residual.
// ---------------------------------------------------------------------------

// dynamic smem layout (floats)
#define OFF_PARTS   0                          // [4][16][68]
#define OFF_PARTV   (OFF_PARTS + 4*16*68)      // [4][48][68]
#define OFF_GS      (OFF_PARTV + 4*48*68)      // [4][132]
#define OFF_SIN     (OFF_GS + 4*132)           // [4][16]
#define OFF_VIN     (OFF_SIN + 64)             // [4][48]
#define OFF_WLS     (OFF_VIN + 192)            // 256
#define OFF_WLV     (OFF_WLS + 256)
#define OFF_WOS     (OFF_WLV + 256)
#define OFF_WOV     (OFF_WOS + 256)
#define OFF_OUTS    (OFF_WOV + 256)            // [4][16]
#define OFF_OUTV    (OFF_OUTS + 64)            // [4][48]
#define OFF_RED     (OFF_OUTV + 192)           // [8]
#define OFF_DSUM    (OFF_RED + 8)              // [1]
#define SMEM_FLOATS (OFF_DSUM + 1)
#define SMEM_BYTES  (SMEM_FLOATS * 4)

__global__ __launch_bounds__(256) void node_kernel(
    const float* __restrict__ node_attr,
    const float* __restrict__ mask,
    const float* __restrict__ w_lin_in_s,
    const float* __restrict__ w_lin_in_v,
    const float* __restrict__ fc_w2,
    const float* __restrict__ fc_b2,
    const float* __restrict__ w_lin_out_s,
    const float* __restrict__ w_lin_out_v,
    float* __restrict__ out)
{
    extern __shared__ __align__(16) float sm[];
    float* partS = sm + OFF_PARTS;
    float* partV = sm + OFF_PARTV;
    float* Gs    = sm + OFF_GS;     // [nl][132]
    float* sinS  = sm + OFF_SIN;    // [nl][16]
    float* vinS  = sm + OFF_VIN;    // [nl][48]
    float* wls   = sm + OFF_WLS;
    float* wlv   = sm + OFF_WLV;
    float* wos   = sm + OFF_WOS;
    float* wov   = sm + OFF_WOV;
    float* outsS = sm + OFF_OUTS;
    float* outvS = sm + OFF_OUTV;
    float* red   = sm + OFF_RED;

    const int t = threadIdx.x;
    const int node0 = blockIdx.x * 4;
    const int b = node0 >> 8;

    // --- phase 0: stage weights, G, mask reduce ---
    wls[t] = w_lin_in_s[t];
    wlv[t] = w_lin_in_v[t];
    wos[t] = w_lin_out_s[t];
    wov[t] = w_lin_out_v[t];
    if (t < 132) {
        #pragma unroll
        for (int nl = 0; nl < 4; nl++) Gs[nl*132 + t] = g_G[node0 + nl][t];
    }
    {
        float mv = mask[b * NN + t];
        #pragma unroll
        for (int o = 16; o; o >>= 1) mv += __shfl_xor_sync(0xFFFFFFFFu, mv, o);
        if ((t & 31) == 0) red[t >> 5] = mv;
    }
    __syncthreads();
    if (t == 0) {
        float s = 0.f;
        #pragma unroll
        for (int i = 0; i < 8; i++) s += red[i];
        sm[OFF_DSUM] = s - 1.0f;
    }

    // --- phase 1: s_in / v_in (irrep_linear on node_attr, /4) ---
    {
        int nl = t >> 6, u = t & 63;
        const float* na = node_attr + (size_t)(node0 + nl) * 64;
        if (u < 16) {
            float s = 0.f;
            #pragma unroll
            for (int i = 0; i < 16; i++) s += na[i] * wls[i * 16 + u];
            sinS[nl*16 + u] = s * 0.25f;
        } else {
            int idx = u - 16;
            int o = idx / 3, x = idx % 3;
            float s = 0.f;
            #pragma unroll
            for (int i = 0; i < 16; i++) s += na[16 + i * 3 + x] * wlv[i * 16 + o];
            vinS[nl*48 + o * 3 + x] = s * 0.25f;
        }
    }
    __syncthreads();

    // --- phase 2: single pass over W2' ---
    const int oq = t & 3;     // which float4 of the 16 o's
    const int g  = t >> 2;    // group in [0,64)

    float accS[4][4];         // [nl][q]  -> out_s[o=oq*4+q]
    float accV[4][12];        // [nl][x*4+q] -> out_v[o=oq*4+q][x]
    #pragma unroll
    for (int nl = 0; nl < 4; nl++) {
        #pragma unroll
        for (int q = 0; q < 4; q++) accS[nl][q] = 0.f;
        #pragma unroll
        for (int q = 0; q < 12; q++) accV[nl][q] = 0.f;
    }

    const float4* W2 = (const float4*)fc_w2;   // 33x1024 -> [f][256] float4
    #pragma unroll 2
    for (int p = 0; p < 8; p++) {
        int idx = p * 64 + g;          // (f,i) pair index in [0,512)
        int f = idx >> 4, i = idx & 15;
        int base = f * 256 + i * 4 + oq;
        float4 wss = W2[base];
        float4 wvv = W2[base + 64];
        float4 wsv = W2[base + 128];
        float4 wvs = W2[base + 192];
        #pragma unroll
        for (int nl = 0; nl < 4; nl++) {
            float g0 = Gs[nl*132 + f*4 + 0];
            float g1 = Gs[nl*132 + f*4 + 1];
            float g2 = Gs[nl*132 + f*4 + 2];
            float g3 = Gs[nl*132 + f*4 + 3];
            float si = sinS[nl*16 + i];
            float v0 = vinS[nl*48 + i*3 + 0];
            float v1 = vinS[nl*48 + i*3 + 1];
            float v2 = vinS[nl*48 + i*3 + 2];
            float a = g0 * si;
            float bc = (g1 * v0 + g2 * v1 + g3 * v2) * RSQRT3;
            accS[nl][0] += a * wss.x + bc * wvv.x;
            accS[nl][1] += a * wss.y + bc * wvv.y;
            accS[nl][2] += a * wss.z + bc * wvv.z;
            accS[nl][3] += a * wss.w + bc * wvv.w;
            float c0 = g1 * si, c1 = g2 * si, c2 = g3 * si;
            float d0 = g0 * v0, d1 = g0 * v1, d2 = g0 * v2;
            accV[nl][0]  += c0 * wsv.x + d0 * wvs.x;
            accV[nl][1]  += c0 * wsv.y + d0 * wvs.y;
            accV[nl][2]  += c0 * wsv.z + d0 * wvs.z;
            accV[nl][3]  += c0 * wsv.w + d0 * wvs.w;
            accV[nl][4]  += c1 * wsv.x + d1 * wvs.x;
            accV[nl][5]  += c1 * wsv.y + d1 * wvs.y;
            accV[nl][6]  += c1 * wsv.z + d1 * wvs.z;
            accV[nl][7]  += c1 * wsv.w + d1 * wvs.w;
            accV[nl][8]  += c2 * wsv.x + d2 * wvs.x;
            accV[nl][9]  += c2 * wsv.y + d2 * wvs.y;
            accV[nl][10] += c2 * wsv.z + d2 * wvs.z;
            accV[nl][11] += c2 * wsv.w + d2 * wvs.w;
        }
    }
    // bias row f=32 (W2' row from fc_b2): pairs (f=32, i=g) for g<16
    if (g < 16) {
        const float4* B2 = (const float4*)fc_b2;
        int i = g;
        int base = i * 4 + oq;
        float4 wss = B2[base];
        float4 wvv = B2[base + 64];
        float4 wsv = B2[base + 128];
        float4 wvs = B2[base + 192];
        #pragma unroll
        for (int nl = 0; nl < 4; nl++) {
            float g0 = Gs[nl*132 + 128 + 0];
            float g1 = Gs[nl*132 + 128 + 1];
            float g2 = Gs[nl*132 + 128 + 2];
            float g3 = Gs[nl*132 + 128 + 3];
            float si = sinS[nl*16 + i];
            float v0 = vinS[nl*48 + i*3 + 0];
            float v1 = vinS[nl*48 + i*3 + 1];
            float v2 = vinS[nl*48 + i*3 + 2];
            float a = g0 * si;
            float bc = (g1 * v0 + g2 * v1 + g3 * v2) * RSQRT3;
            accS[nl][0] += a * wss.x + bc * wvv.x;
            accS[nl][1] += a * wss.y + bc * wvv.y;
            accS[nl][2] += a * wss.z + bc * wvv.z;
            accS[nl][3] += a * wss.w + bc * wvv.w;
            float c0 = g1 * si, c1 = g2 * si, c2 = g3 * si;
            float d0 = g0 * v0, d1 = g0 * v1, d2 = g0 * v2;
            accV[nl][0]  += c0 * wsv.x + d0 * wvs.x;
            accV[nl][1]  += c0 * wsv.y + d0 * wvs.y;
            accV[nl][2]  += c0 * wsv.z + d0 * wvs.z;
            accV[nl][3]  += c0 * wsv.w + d0 * wvs.w;
            accV[nl][4]  += c1 * wsv.x + d1 * wvs.x;
            accV[nl][5]  += c1 * wsv.y + d1 * wvs.y;
            accV[nl][6]  += c1 * wsv.z + d1 * wvs.z;
            accV[nl][7]  += c1 * wsv.w + d1 * wvs.w;
            accV[nl][8]  += c2 * wsv.x + d2 * wvs.x;
            accV[nl][9]  += c2 * wsv.y + d2 * wvs.y;
            accV[nl][10] += c2 * wsv.z + d2 * wvs.z;
            accV[nl][11] += c2 * wsv.w + d2 * wvs.w;
        }
    }

    // stage partials: partS[nl][o][g] (rows padded to 68), partV[nl][o*3+x][g]
    #pragma unroll
    for (int nl = 0; nl < 4; nl++) {
        #pragma unroll
        for (int q = 0; q < 4; q++)
            partS[(nl*16 + oq*4 + q) * 68 + g] = accS[nl][q];
        #pragma unroll
        for (int x = 0; x < 3; x++)
            #pragma unroll
            for (int q = 0; q < 4; q++)
                partV[(nl*48 + (oq*4 + q)*3 + x) * 68 + g] = accV[nl][x*4 + q];
    }
    __syncthreads();

    // --- phase 3: reduce over 64 groups, apply scale ---
    {
        float scale = INV_FAN / sm[OFF_DSUM];
        if (t < 64) {
            int nl = t >> 4, o = t & 15;
            const float4* row = (const float4*)(partS + (nl*16 + o) * 68);
            float s = 0.f;
            #pragma unroll
            for (int j = 0; j < 16; j++) {
                float4 v = row[j];
                s += (v.x + v.y) + (v.z + v.w);
            }
            outsS[nl*16 + o] = s * scale;
        } else {
            int u = t - 64;
            int nl = u / 48, j = u % 48;
            const float4* row = (const float4*)(partV + (nl*48 + j) * 68);
            float s = 0.f;
            #pragma unroll
            for (int k = 0; k < 16; k++) {
                float4 v = row[k];
                s += (v.x + v.y) + (v.z + v.w);
            }
            outvS[nl*48 + j] = s * scale;
        }
    }
    __syncthreads();

    // --- phase 4: output linear (/4) + residual ---
    {
        int nl = t >> 6, u = t & 63;
        const float* na = node_attr + (size_t)(node0 + nl) * 64;
        float r;
        if (u < 16) {
            float s = 0.f;
            #pragma unroll
            for (int o = 0; o < 16; o++) s += outsS[nl*16 + o] * wos[o * 16 + u];
            r = s * 0.25f + na[u];
        } else {
            int idx = u - 16;
            int o2 = idx / 3, x = idx % 3;
            float s = 0.f;
            #pragma unroll
            for (int o = 0; o < 16; o++) s += outvS[nl*48 + o * 3 + x] * wov[o * 16 + o2];
            r = s * 0.25f + na[u];
        }
        out[(size_t)(node0 + nl) * 64 + u] = r;
    }
}

extern "C" void kernel_launch(void* const* d_in, const int* in_sizes, int n_in,
                              void* d_out, int out_size) {
    const float* node_attr    = (const float*)d_in[0];
    const float* edge_attr    = (const float*)d_in[1];
    const float* edge_sh      = (const float*)d_in[2];
    const float* mask         = (const float*)d_in[3];
    const float* w_lin_in_s   = (const float*)d_in[4];
    const float* w_lin_in_v   = (const float*)d_in[5];
    const float* fc_w1        = (const float*)d_in[6];
    const float* fc_b1        = (const float*)d_in[7];
    const float* fc_w2        = (const float*)d_in[8];
    const float* fc_b2        = (const float*)d_in[9];
    const float* w_lin_out_s  = (const float*)d_in[10];
    const float* w_lin_out_v  = (const float*)d_in[11];
    float* out = (float*)d_out;

    cudaFuncSetAttribute(node_kernel,
                         cudaFuncAttributeMaxDynamicSharedMemorySize, SMEM_BYTES);

    edge_kernel<<<NNODE, 256>>>(edge_attr, edge_sh, mask, fc_w1, fc_b1);
    node_kernel<<<NNODE / 4, 256, SMEM_BYTES>>>(node_attr, mask,
                                    w_lin_in_s, w_lin_in_v,
                                    fc_w2, fc_b2, w_lin_out_s, w_lin_out_v, out);
}